// round 14
// baseline (speedup 1.0000x reference)
#include <cuda_runtime.h>
#include <cstdint>
#include <math.h>

#define BB 64
#define AA 8400
#define CC 80
#define KK 300
#define HF 160
#define WF 160
#define NBINS 4096
#define CAP 4096
#define THRESH 0.25f
#define FIELD_N (HF * WF)
#define APB (AA / 4)          // anchors per block = 2100

// scratch (no allocations allowed)
__device__ float g_scores[BB * AA];
__device__ float g_beta[BB * AA];
__device__ int   g_cls[BB * AA];

// smem layout: field[25600] | s_m[2100] | s_am[2100 bytes]
#define SMEM_BYTES (FIELD_N * 4 + APB * 4 + APB)

// ---------------- Fused kernel: field-pool beta + cls max/argmax + score ----------------
__global__ __launch_bounds__(1024) void fused_kernel(const float4* __restrict__ boxes,
                                                     const float*  __restrict__ obj,
                                                     const float4* __restrict__ cls,
                                                     const float*  __restrict__ field) {
    extern __shared__ float smem[];
    float* sfield = smem;                       // 25600 floats
    float* s_m    = smem + FIELD_N;             // 2100 floats
    uint8_t* s_am = (uint8_t*)(s_m + APB);      // 2100 bytes

    int b = blockIdx.x >> 2;
    int part = blockIdx.x & 3;
    int tid = threadIdx.x;
    const int a0 = part * APB;
    const int ibase = b * AA + a0;

    // --- stage field into smem (float4) ---
    {
        const float4* f4 = (const float4*)(field + (size_t)b * FIELD_N);
        for (int j = tid; j < FIELD_N / 4; j += 1024)
            ((float4*)sfield)[j] = f4[j];
    }

    // --- cls max/argmax: 4 lanes per anchor, 8 anchors per warp ---
    // Loop condition is warp-uniform; out-of-range lanes clamp their anchor
    // index (redundant load) so the full-mask shuffles are always executed by
    // all 32 lanes. Only the final store is predicated on validity.
    {
        int warp = tid >> 5;
        int lane = tid & 31;
        int sub = lane & 3;
        int q = lane >> 2;
        for (int base = warp * 8; base < APB; base += 32 * 8) {
            int local = base + q;
            bool valid = (local < APB);
            int lc = valid ? local : (APB - 1);
            const float4* cp = cls + (size_t)(ibase + lc) * (CC / 4);
            float m = -1e30f;
            int am = 0;
#pragma unroll
            for (int k = 0; k < 5; k++) {
                int j = k * 4 + sub;
                float4 v4 = cp[j];
                int cb = 4 * j;
                if (v4.x > m) { m = v4.x; am = cb + 0; }
                if (v4.y > m) { m = v4.y; am = cb + 1; }
                if (v4.z > m) { m = v4.z; am = cb + 2; }
                if (v4.w > m) { m = v4.w; am = cb + 3; }
            }
#pragma unroll
            for (int off = 1; off < 4; off <<= 1) {
                float m2 = __shfl_xor_sync(0xffffffffu, m, off);
                int a2 = __shfl_xor_sync(0xffffffffu, am, off);
                if (m2 > m || (m2 == m && a2 < am)) { m = m2; am = a2; }
            }
            if (sub == 0 && valid) {
                s_m[local] = m;
                s_am[local] = (uint8_t)am;
            }
        }
    }
    __syncthreads();

    // --- beta pool from smem field + final score ---
    for (int t = tid; t < APB; t += 1024) {
        int i = ibase + t;
        float4 bx = boxes[i];
        float x1 = bx.x, y1 = bx.y, x2 = bx.z, y2 = bx.w;

        float beta = 0.0f;
#pragma unroll
        for (int jy = 0; jy < 3; jy++) {
            float ty = (jy + 0.5f) * (1.0f / 3.0f);
            float ys = y1 + ty * (y2 - y1);
            float v = ys * 0.25f - 0.5f;
            v = fminf(fmaxf(v, 0.0f), (float)(HF - 1));
            float v0f = floorf(v);
            float fv = v - v0f;
            int v0 = (int)v0f;
            int v1 = min(v0 + 1, HF - 1);
#pragma unroll
            for (int jx = 0; jx < 3; jx++) {
                float tx = (jx + 0.5f) * (1.0f / 3.0f);
                float xs = x1 + tx * (x2 - x1);
                float u = xs * 0.25f - 0.5f;
                u = fminf(fmaxf(u, 0.0f), (float)(WF - 1));
                float u0f = floorf(u);
                float fu = u - u0f;
                int u0 = (int)u0f;
                int u1 = min(u0 + 1, WF - 1);
                float f00 = sfield[v0 * WF + u0];
                float f01 = sfield[v0 * WF + u1];
                float f10 = sfield[v1 * WF + u0];
                float f11 = sfield[v1 * WF + u1];
                beta += f00 * (1.0f - fv) * (1.0f - fu)
                      + f01 * (1.0f - fv) * fu
                      + f10 * fv * (1.0f - fu)
                      + f11 * fv * fu;
            }
        }
        beta *= (1.0f / 9.0f);

        float area = fmaxf(x2 - x1, 0.0f) * fmaxf(y2 - y1, 0.0f) * (1.0f / (640.0f * 640.0f));
        float bs = beta * ((area < 0.01f) ? 1.5f : 1.0f);

        float m = s_m[t];
        int am = (int)s_am[t];
        float best_cls_score = 1.0f / (1.0f + expf(-(m - 0.5f * bs)));
        float sobj = 1.0f / (1.0f + expf(-(obj[i] - bs)));

        g_scores[i] = sobj * best_cls_score;
        g_beta[i] = bs;
        g_cls[i] = am;
    }
}

// ---------------- Phase 2: histogram cutoff + rank-by-counting emit ----------------
__global__ __launch_bounds__(1024) void phase2_kernel(const float4* __restrict__ boxes,
                                                      float* __restrict__ out) {
    int b = blockIdx.x;
    int tid = threadIdx.x;

    __shared__ unsigned long long s_cand[CAP];        // 32KB; first 16KB aliased as histogram
    unsigned int* s_hist = (unsigned int*)s_cand;
    __shared__ unsigned int s_warp[32];
    __shared__ int s_cutoff;
    __shared__ int s_cnt;

    for (int j = tid; j < NBINS; j += 1024) s_hist[j] = 0;
    if (tid == 0) { s_cutoff = 0; s_cnt = 0; }
    __syncthreads();

    const float* sc = g_scores + (size_t)b * AA;
    for (int a = tid; a < AA; a += 1024) {
        float s = sc[a];
        if (s >= THRESH) {
            int bin = (int)((s - THRESH) * (NBINS / 0.75f));
            bin = max(0, min(NBINS - 1, bin));
            atomicAdd(&s_hist[bin], 1u);
        }
    }
    __syncthreads();

    // suffix scan from top bins, find cutoff bin covering rank K
    {
        int g = 1023 - tid;
        int base = 4 * g;
        unsigned int c0 = s_hist[base + 3];
        unsigned int c1 = s_hist[base + 2];
        unsigned int c2 = s_hist[base + 1];
        unsigned int c3 = s_hist[base + 0];
        unsigned int i0 = c0;
        unsigned int i1 = i0 + c1;
        unsigned int i2 = i1 + c2;
        unsigned int i3 = i2 + c3;
        unsigned int ts = i3;

        unsigned int v = ts;
        int lane = tid & 31;
        int w = tid >> 5;
#pragma unroll
        for (int off = 1; off < 32; off <<= 1) {
            unsigned int n = __shfl_up_sync(0xffffffffu, v, off);
            if (lane >= off) v += n;
        }
        if (lane == 31) s_warp[w] = v;
        __syncthreads();
        if (tid < 32) {
            unsigned int x = s_warp[tid];
            unsigned int incl = x;
#pragma unroll
            for (int off = 1; off < 32; off <<= 1) {
                unsigned int n = __shfl_up_sync(0xffffffffu, incl, off);
                if (tid >= off) incl += n;
            }
            s_warp[tid] = incl - x;
        }
        __syncthreads();
        unsigned int texcl = s_warp[w] + (v - ts);

        if (texcl + i0 >= KK) atomicMax(&s_cutoff, base + 3);
        if (texcl + i1 >= KK) atomicMax(&s_cutoff, base + 2);
        if (texcl + i2 >= KK) atomicMax(&s_cutoff, base + 1);
        if (texcl + i3 >= KK) atomicMax(&s_cutoff, base + 0);
    }
    __syncthreads();
    int cutoff = s_cutoff;
    __syncthreads();   // done reading hist before cand overwrites it

    // gather candidates (bin >= cutoff) as packed sort keys
    for (int a = tid; a < AA; a += 1024) {
        float s = sc[a];
        if (s >= THRESH) {
            int bin = (int)((s - THRESH) * (NBINS / 0.75f));
            bin = max(0, min(NBINS - 1, bin));
            if (bin >= cutoff) {
                int p = atomicAdd(&s_cnt, 1);
                if (p < CAP) {
                    unsigned long long key =
                        ((unsigned long long)__float_as_uint(s) << 32) |
                        (unsigned long long)(0xFFFFFFFFu ^ (unsigned int)a);
                    s_cand[p] = key;
                }
            }
        }
    }
    __syncthreads();
    int M = min(s_cnt, CAP);

    // rank-by-counting: keys are unique -> ranks form a permutation of 0..M-1
    const int OFF_S = BB * KK * 4;
    const int OFF_C = OFF_S + BB * KK;
    const int OFF_U = OFF_C + BB * KK;
    const int OFF_V = OFF_U + BB * KK;

    for (int ii = tid; ii < M; ii += 1024) {
        unsigned long long ki = s_cand[ii];
        int rank = 0;
        for (int j = 0; j < M; j++)                 // broadcast LDS reads
            rank += (s_cand[j] > ki) ? 1 : 0;
        if (rank < KK) {
            int o = b * KK + rank;
            float s = __uint_as_float((unsigned int)(ki >> 32));
            int a = (int)(((unsigned int)ki) ^ 0xFFFFFFFFu);
            float4 bb4 = boxes[(size_t)b * AA + a];
            out[o * 4 + 0] = bb4.x;
            out[o * 4 + 1] = bb4.y;
            out[o * 4 + 2] = bb4.z;
            out[o * 4 + 3] = bb4.w;
            out[OFF_S + o] = s;
            out[OFF_C + o] = (float)g_cls[(size_t)b * AA + a];
            out[OFF_U + o] = g_beta[(size_t)b * AA + a];
            out[OFF_V + o] = 1.0f;
        }
    }
    // zero-fill unused slots
    for (int t = tid; t < KK; t += 1024) {
        if (t >= M) {
            int o = b * KK + t;
            out[o * 4 + 0] = 0.0f;
            out[o * 4 + 1] = 0.0f;
            out[o * 4 + 2] = 0.0f;
            out[o * 4 + 3] = 0.0f;
            out[OFF_S + o] = 0.0f;
            out[OFF_C + o] = 0.0f;
            out[OFF_U + o] = 0.0f;
            out[OFF_V + o] = 0.0f;
        }
    }
}

extern "C" void kernel_launch(void* const* d_in, const int* in_sizes, int n_in,
                              void* d_out, int out_size) {
    const float4* boxes = (const float4*)d_in[0];   // [B, A, 4]
    const float*  obj   = (const float*)d_in[1];    // [B, A]
    const float4* cls   = (const float4*)d_in[2];   // [B, A, C]
    const float*  field = (const float*)d_in[3];    // [B, HF, WF]
    float* out = (float*)d_out;

    cudaFuncSetAttribute(fused_kernel, cudaFuncAttributeMaxDynamicSharedMemorySize,
                         SMEM_BYTES);

    fused_kernel<<<BB * 4, 1024, SMEM_BYTES>>>(boxes, obj, cls, field);
    phase2_kernel<<<BB, 1024>>>(boxes, out);
}